// round 2
// baseline (speedup 1.0000x reference)
#include <cuda_runtime.h>

// AdderNet layer: out[n,h,w,f] = sum_{dh,dw,c} |Xpad[n,h+dh,w+dw,c] - filters[f,dh,dw,c]|
// X: [8,32,32,32] f32, filters: [64,3,3,32] f32, out: [8,32,32,64] f32, pad=1, stride=1.

#define N_IMG 8
#define HDIM 32
#define WDIM 32
#define CH 32
#define F_OUT 64
#define KKN 288            // 3*3*32
#define WPAD 34            // w in [-1, 32]

#define XS_ELEMS (3 * CH * WPAD)        // 3264 floats
#define FS_ELEMS (KKN * F_OUT)          // 18432 floats
#define SMEM_BYTES ((XS_ELEMS + FS_ELEMS) * 4)

__device__ __forceinline__ unsigned long long f32x2_add(unsigned long long a,
                                                        unsigned long long b) {
    unsigned long long r;
    asm("add.rn.f32x2 %0, %1, %2;" : "=l"(r) : "l"(a), "l"(b));
    return r;
}

__device__ __forceinline__ unsigned long long pack_dup(float x) {
    unsigned long long r;
    asm("mov.b64 %0, {%1, %1};" : "=l"(r) : "f"(x));
    return r;
}

__global__ __launch_bounds__(256, 2)
void adder_layer_kernel(const float* __restrict__ X,
                        const float* __restrict__ Fw,
                        float* __restrict__ out) {
    extern __shared__ float smem[];
    float* Xs = smem;                 // [3][CH][WPAD]  (row, channel, padded-w)
    float* Fs = smem + XS_ELEMS;      // [KKN][F_OUT]   (negated filters)

    const int tid = threadIdx.x;
    const int n = blockIdx.x >> 5;
    const int h = blockIdx.x & 31;

    // --- Load negated filters: Fs[kk*64 + f] = -Fw[f*288 + kk] ---
    for (int i = tid; i < F_OUT * KKN; i += 256) {
        int f = i / KKN;
        int kk = i - f * KKN;
        Fs[kk * F_OUT + f] = -Fw[i];
    }

    // --- Load 3 input rows, transposed to [c][w], zero-padded ---
    for (int dh = 0; dh < 3; dh++) {
        int row = h - 1 + dh;
        for (int i = tid; i < CH * WPAD; i += 256) {
            // i = wp*CH + c for coalesced global reads (c fastest)
            int wp = i >> 5;          // 0..33 (i < 34*32)
            int c = i & 31;
            int w = wp - 1;
            float v = 0.0f;
            if (row >= 0 && row < HDIM && w >= 0 && w < WDIM)
                v = X[(((n * HDIM) + row) * WDIM + w) * CH + c];
            Xs[(dh * CH + c) * WPAD + wp] = v;
        }
    }
    __syncthreads();

    const int w = tid & 31;           // output w position
    const int g = tid >> 5;           // filter group 0..7 -> pairs 4g..4g+3 -> f = 8g..8g+7

    const unsigned long long ABSMASK = 0x7FFFFFFF7FFFFFFFULL;

    unsigned long long acc0 = 0ull, acc1 = 0ull, acc2 = 0ull, acc3 = 0ull;

    // Filter pairs viewed as u64: index kk*32 + pidx
    const unsigned long long* Fp = reinterpret_cast<const unsigned long long*>(Fs);

    #pragma unroll
    for (int dh = 0; dh < 3; dh++) {
        #pragma unroll
        for (int dw = 0; dw < 3; dw++) {
            const float* xp = &Xs[(dh * CH) * WPAD + (w + dw)];
            const unsigned long long* fb = Fp + ((dh * 3 + dw) * CH) * 32 + (g * 4);
            #pragma unroll 4
            for (int c = 0; c < CH; c++) {
                unsigned long long xx = pack_dup(xp[c * WPAD]);
                const unsigned long long* fk = fb + c * 32;
                unsigned long long f0 = fk[0];
                unsigned long long f1 = fk[1];
                unsigned long long f2 = fk[2];
                unsigned long long f3 = fk[3];
                unsigned long long d0 = f32x2_add(xx, f0) & ABSMASK;
                unsigned long long d1 = f32x2_add(xx, f1) & ABSMASK;
                unsigned long long d2 = f32x2_add(xx, f2) & ABSMASK;
                unsigned long long d3 = f32x2_add(xx, f3) & ABSMASK;
                acc0 = f32x2_add(acc0, d0);
                acc1 = f32x2_add(acc1, d1);
                acc2 = f32x2_add(acc2, d2);
                acc3 = f32x2_add(acc3, d3);
            }
        }
    }

    // Output: thread writes f = 8g .. 8g+7 at (n,h,w)
    unsigned long long* o = reinterpret_cast<unsigned long long*>(
        out + ((((n * HDIM) + h) * WDIM + w) * F_OUT + g * 8));
    o[0] = acc0;
    o[1] = acc1;
    o[2] = acc2;
    o[3] = acc3;
}

extern "C" void kernel_launch(void* const* d_in, const int* in_sizes, int n_in,
                              void* d_out, int out_size) {
    const float* X = (const float*)d_in[0];
    const float* Fw = (const float*)d_in[1];
    float* out = (float*)d_out;

    cudaFuncSetAttribute(adder_layer_kernel,
                         cudaFuncAttributeMaxDynamicSharedMemorySize, SMEM_BYTES);
    adder_layer_kernel<<<N_IMG * HDIM, 256, SMEM_BYTES>>>(X, Fw, out);
}

// round 3
// speedup vs baseline: 1.2133x; 1.2133x over previous
#include <cuda_runtime.h>

// AdderNet: out[n,h,w,f] = sum_{dh,dw,c} |Xpad[n,h+dh-1,w+dw-1,c] - F[f,dh,dw,c]|
// X [8,32,32,32] f32, F [64,3,3,32] f32, out [8,32,32,64] f32.
//
// Grid: (256 nh, 2 fhalf). Block 256 = wq(16) x g(16).
// Thread: 2 pixels (w=2wq, 2wq+1) x 2 filters (one packed f32x2 pair).
// Smem: X rows duplicated as {v,v} u64 (no dup movs, x reused over all taps),
//       filters negated+paired, c-contiguous for LDS.128 over c.

#define CH 32
#define WPAD 34
#define XS_U64 (3 * CH * WPAD)     // 3264
#define FS_U64 (16 * 288)          // 4608 (16 pairs x 9 taps x 32 c)
#define SMEM_BYTES ((XS_U64 + FS_U64) * 8)   // 62976

typedef unsigned long long u64;

__device__ __forceinline__ u64 f32x2_add(u64 a, u64 b) {
    u64 r;
    asm("add.rn.f32x2 %0, %1, %2;" : "=l"(r) : "l"(a), "l"(b));
    return r;
}

__device__ __forceinline__ u64 pack_dup(float x) {
    u64 r;
    asm("mov.b64 %0, {%1, %1};" : "=l"(r) : "f"(x));
    return r;
}

__device__ __forceinline__ u64 pack2(float lo, float hi) {
    u64 r;
    asm("mov.b64 %0, {%1, %2};" : "=l"(r) : "f"(lo), "f"(hi));
    return r;
}

__global__ __launch_bounds__(256, 3)
void adder_layer_kernel(const float* __restrict__ X,
                        const float* __restrict__ Fw,
                        float* __restrict__ out) {
    extern __shared__ __align__(16) u64 smem[];
    u64* Xs = smem;              // [(dh*32+c)*34 + wp], value = {v,v}
    u64* Fs = smem + XS_U64;     // [p*288 + (dh*3+dw)*32 + c] = {-f(2p), -f(2p+1)}

    const int tid = threadIdx.x;
    const int nh = blockIdx.x;           // n*32 + h
    const int fbase = blockIdx.y * 32;   // filter half
    const int n = nh >> 5;
    const int h = nh & 31;

    // ---- Fill filter pairs (negated): 4608 u64, 18 iters/thread ----
    for (int i = tid; i < FS_U64; i += 256) {
        int p = i >> 8;                  // i / 288? no: use div
        p = i / 288;
        int rem = i - p * 288;           // (dh*3+dw)*32 + c, matches global kk order
        int f0 = (fbase + 2 * p) * 288 + rem;
        Fs[i] = pack2(-Fw[f0], -Fw[f0 + 288]);
    }

    // ---- Fill X rows, transposed to [dh][c][wp], duplicated {v,v} ----
    for (int i = tid; i < XS_U64; i += 256) {
        int c = i & 31;                  // c fastest -> coalesced global reads
        int t = i >> 5;
        int wp = t % WPAD;
        int dh = t / WPAD;
        int row = h - 1 + dh;
        int w = wp - 1;
        float v = 0.0f;
        if (row >= 0 && row < 32 && w >= 0 && w < 32)
            v = X[(((n * 32) + row) * 32 + w) * CH + c];
        Xs[(dh * CH + c) * WPAD + wp] = pack_dup(v);
    }
    __syncthreads();

    const int wq = tid & 15;
    const int g = tid >> 4;              // pair index 0..15
    const int w0 = 2 * wq;               // pixel wp base (wp = w, w+1 ... covers taps)

    const u64 ABSMASK = 0x7FFFFFFF7FFFFFFFULL;

    // 4 accumulator chains: [pixel][c parity]
    u64 acc00 = 0ull, acc01 = 0ull, acc10 = 0ull, acc11 = 0ull;

    #pragma unroll
    for (int dh = 0; dh < 3; dh++) {
        const u64* xbase = Xs + (dh * CH) * WPAD + w0;
        const u64* fb = Fs + g * 288 + dh * 96;
        #pragma unroll 2
        for (int c2 = 0; c2 < 16; c2++) {
            int c = 2 * c2;
            // x for c: 4 dup'd u64 covering wp = w0..w0+3 (all taps, both pixels)
            const ulonglong2* xr0 = reinterpret_cast<const ulonglong2*>(xbase + c * WPAD);
            const ulonglong2* xr1 = reinterpret_cast<const ulonglong2*>(xbase + (c + 1) * WPAD);
            ulonglong2 xA0 = xr0[0], xB0 = xr0[1];
            ulonglong2 xA1 = xr1[0], xB1 = xr1[1];
            u64 x0[4] = {xA0.x, xA0.y, xB0.x, xB0.y};
            u64 x1[4] = {xA1.x, xA1.y, xB1.x, xB1.y};

            // filters: 3 taps x 2 c's
            ulonglong2 f0 = *reinterpret_cast<const ulonglong2*>(fb + 0 * 32 + c);
            ulonglong2 f1 = *reinterpret_cast<const ulonglong2*>(fb + 1 * 32 + c);
            ulonglong2 f2 = *reinterpret_cast<const ulonglong2*>(fb + 2 * 32 + c);
            u64 fc0[3] = {f0.x, f1.x, f2.x};   // c
            u64 fc1[3] = {f0.y, f1.y, f2.y};   // c+1

            #pragma unroll
            for (int dw = 0; dw < 3; dw++) {
                u64 d;
                d = f32x2_add(x0[dw],     fc0[dw]) & ABSMASK; acc00 = f32x2_add(acc00, d);
                d = f32x2_add(x0[dw + 1], fc0[dw]) & ABSMASK; acc10 = f32x2_add(acc10, d);
                d = f32x2_add(x1[dw],     fc1[dw]) & ABSMASK; acc01 = f32x2_add(acc01, d);
                d = f32x2_add(x1[dw + 1], fc1[dw]) & ABSMASK; acc11 = f32x2_add(acc11, d);
            }
        }
    }

    u64 accP0 = f32x2_add(acc00, acc01);   // pixel w0
    u64 accP1 = f32x2_add(acc10, acc11);   // pixel w0+1

    // out[((nh)*32 + w)*64 + fbase + 2g], two filters per u64 store
    u64* o0 = reinterpret_cast<u64*>(out + ((nh * 32) + w0) * 64 + fbase + 2 * g);
    u64* o1 = reinterpret_cast<u64*>(out + ((nh * 32) + w0 + 1) * 64 + fbase + 2 * g);
    *o0 = accP0;
    *o1 = accP1;
}

extern "C" void kernel_launch(void* const* d_in, const int* in_sizes, int n_in,
                              void* d_out, int out_size) {
    const float* X = (const float*)d_in[0];
    const float* Fw = (const float*)d_in[1];
    float* out = (float*)d_out;

    cudaFuncSetAttribute(adder_layer_kernel,
                         cudaFuncAttributeMaxDynamicSharedMemorySize, SMEM_BYTES);
    dim3 grid(256, 2);
    adder_layer_kernel<<<grid, 256, SMEM_BYTES>>>(X, Fw, out);
}

// round 4
// speedup vs baseline: 1.8722x; 1.5431x over previous
#include <cuda_runtime.h>

// AdderNet: out[n,h,w,f] = sum_{dh,dw,c} |Xpad[n,h+dh-1,w+dw-1,c] - F[f,dh,dw,c]|
// X [8,32,32,32] f32 NHWC, F [64,3,3,32] f32, out [8,32,32,64] f32.
//
// f32x2 lanes pack CHANNEL pairs (c, c+1): both operands naturally contiguous,
// no duplication, no filter preprocessing. diff = fma.f32x2(f, -1, x).
// Grid 256 (one nh row per block). Block 256 = wq(8) x fg(32).
// Thread: 4 pixels (w = 4wq..4wq+3) x 2 filters (2fg, 2fg+1), 8 outputs.
// X smem pi-swizzled [dh][c4][r*9+q] (wp = 4q+r) -> conflict-free LDS.128.

#define XS_F4 (3 * 8 * 36)        // 864 float4 (3 rows, 8 c-quads, 36 slots)
#define FS_F4 (64 * 288 / 4)      // 4608 float4 (raw filter copy)
#define SMEM_BYTES ((XS_F4 + FS_F4) * 16)   // 87,552 B

typedef unsigned long long u64;

__device__ __forceinline__ u64 ffma2(u64 a, u64 b, u64 c) {   // a*b + c (packed)
    u64 r;
    asm("fma.rn.f32x2 %0, %1, %2, %3;" : "=l"(r) : "l"(a), "l"(b), "l"(c));
    return r;
}
__device__ __forceinline__ u64 fadd2(u64 a, u64 b) {
    u64 r;
    asm("add.rn.f32x2 %0, %1, %2;" : "=l"(r) : "l"(a), "l"(b));
    return r;
}

__global__ __launch_bounds__(256, 2)
void adder_layer_kernel(const float* __restrict__ X,
                        const float* __restrict__ Fw,
                        float* __restrict__ out) {
    extern __shared__ __align__(16) float4 smem4[];
    float4* Xs4 = smem4;              // [(dh*8 + c4)*36 + s],  s = r*9 + q, wp = 4q + r
    float4* Fs4 = smem4 + XS_F4;      // raw [f][kk] copy, float4 over c

    const int tid = threadIdx.x;
    const int nh = blockIdx.x;        // n*32 + h
    const int n = nh >> 5;
    const int h = nh & 31;

    // ---- Filter fill: straight coalesced copy (no transform needed) ----
    const float4* Fg4 = reinterpret_cast<const float4*>(Fw);
    for (int i = tid; i < FS_F4; i += 256) Fs4[i] = Fg4[i];

    // ---- X fill: 3 rows, pi-swizzled over wp, zero-padded ----
    const float4* Xg4 = reinterpret_cast<const float4*>(X);
    for (int i = tid; i < XS_F4; i += 256) {
        int c4 = i & 7;
        int t = i >> 3;
        int s = t % 36;               // storage slot
        int dh = t / 36;
        int q = s % 9, r = s / 9;
        int wp = 4 * q + r;           // logical padded-w position
        int row = h - 1 + dh;
        int w = wp - 1;
        float4 v = make_float4(0.f, 0.f, 0.f, 0.f);
        if (row >= 0 && row < 32 && w >= 0 && w < 32)
            v = Xg4[(((n * 32) + row) * 32 + w) * 8 + c4];
        Xs4[(dh * 8 + c4) * 36 + s] = v;
    }
    __syncthreads();

    const int wq = tid & 7;           // pixel group: w = 4wq .. 4wq+3
    const int fg = tid >> 3;          // 0..31 -> filters 2fg, 2fg+1

    const u64 NEG1 = 0xBF800000BF800000ULL;   // {-1.0f, -1.0f}
    const u64 ABSM = 0x7FFFFFFF7FFFFFFFULL;

    u64 acc[2][4];
    #pragma unroll
    for (int fi = 0; fi < 2; fi++)
        #pragma unroll
        for (int p = 0; p < 4; p++) acc[fi][p] = 0ull;

    const ulonglong2* Xu = reinterpret_cast<const ulonglong2*>(Xs4);
    const ulonglong2* Fu = reinterpret_cast<const ulonglong2*>(Fs4);

    #pragma unroll
    for (int dh = 0; dh < 3; dh++) {
        #pragma unroll 2
        for (int c4 = 0; c4 < 8; c4++) {
            const ulonglong2* xr = Xu + (dh * 8 + c4) * 36;
            // x[k] = 4 channels at wp = 4wq + k   (k = 0..5)
            ulonglong2 x[6];
            x[0] = xr[wq];
            x[1] = xr[9 + wq];
            x[2] = xr[18 + wq];
            x[3] = xr[27 + wq];
            x[4] = xr[wq + 1];        // slot r=0, q=wq+1 -> wp = 4wq+4
            x[5] = xr[9 + wq + 1];    // slot r=1, q=wq+1 -> wp = 4wq+5

            #pragma unroll
            for (int fi = 0; fi < 2; fi++) {
                const int f = 2 * fg + fi;
                const ulonglong2* fr = Fu + f * 72 + dh * 24 + c4;  // float4 units
                ulonglong2 tt[3];
                tt[0] = fr[0];        // tap dw=0, 4 channels
                tt[1] = fr[8];        // tap dw=1
                tt[2] = fr[16];       // tap dw=2

                #pragma unroll
                for (int p = 0; p < 4; p++) {
                    #pragma unroll
                    for (int dw = 0; dw < 3; dw++) {
                        const ulonglong2 xx = x[p + dw];
                        u64 dlo = ffma2(tt[dw].x, NEG1, xx.x) & ABSM;
                        u64 dhi = ffma2(tt[dw].y, NEG1, xx.y) & ABSM;
                        acc[fi][p] = fadd2(acc[fi][p], dlo);
                        acc[fi][p] = fadd2(acc[fi][p], dhi);
                    }
                }
            }
        }
    }

    // ---- Epilogue: horizontal add of the two packed lanes, store float2 ----
    #pragma unroll
    for (int p = 0; p < 4; p++) {
        float r0, r1;
        {
            u64 a = acc[0][p];
            r0 = __uint_as_float((unsigned)a) + __uint_as_float((unsigned)(a >> 32));
        }
        {
            u64 a = acc[1][p];
            r1 = __uint_as_float((unsigned)a) + __uint_as_float((unsigned)(a >> 32));
        }
        float2 v = make_float2(r0, r1);
        *reinterpret_cast<float2*>(out + ((nh * 32) + 4 * wq + p) * 64 + 2 * fg) = v;
    }
}

extern "C" void kernel_launch(void* const* d_in, const int* in_sizes, int n_in,
                              void* d_out, int out_size) {
    const float* X = (const float*)d_in[0];
    const float* Fw = (const float*)d_in[1];
    float* out = (float*)d_out;

    cudaFuncSetAttribute(adder_layer_kernel,
                         cudaFuncAttributeMaxDynamicSharedMemorySize, SMEM_BYTES);
    adder_layer_kernel<<<256, 256, SMEM_BYTES>>>(X, Fw, out);
}